// round 14
// baseline (speedup 1.0000x reference)
#include <cuda_runtime.h>
#include <cuda_fp16.h>
#include <cstdint>

#define BATCH  256
#define DIM    4096
#define BD     (BATCH * DIM)
#define NSTEPS 30
#define SMEM_BYTES 81920    // 2 stages x (32KB A + 8KB W), NT=64 worst case

// ---------------- persistent device scratch (packed, pre-swizzled) ----------------
// Weights: [N/NTp][64 kTiles][NTp rows][64 halfs], chunk c of row stored at c^(row&7)
__device__ __align__(128) __half gW0[(size_t)DIM * DIM];   // NTp=64
__device__ __align__(128) __half gW1[(size_t)DIM * DIM];   // NTp=32
__device__ __align__(128) __half gW2[(size_t)DIM * DIM];   // NTp=32
__device__ __align__(128) __half gW3[(size_t)DIM * DIM];   // NTp=64
__device__ __align__(128) __half gW4[(size_t)DIM * DIM];   // NTp=32
__device__ float g_sf[2][3][BD];                            // fp32 state (plain)
__device__ __align__(128) __half g_sh[2][3][BD];            // f16 state, panel-packed [64][256][64]
__device__ __align__(128) __half g_s3h[BD];                 // f16 data layer, panel-packed
__device__ float g_top[BD];                                 // s3 @ W4^T (plain fp32)

// ---------------- helpers ----------------
__device__ __forceinline__ uint32_t s2u(const void* p) {
    return (uint32_t)__cvta_generic_to_shared(p);
}
__device__ __forceinline__ void mbar_init(uint32_t a, uint32_t c) {
    asm volatile("mbarrier.init.shared.b64 [%0], %1;" :: "r"(a), "r"(c) : "memory");
}
__device__ __forceinline__ void mbar_arrive(uint32_t a) {
    asm volatile("mbarrier.arrive.shared.b64 _, [%0];" :: "r"(a) : "memory");
}
__device__ __forceinline__ void mbar_expect(uint32_t a, uint32_t tx) {
    asm volatile("mbarrier.arrive.expect_tx.shared.b64 _, [%0], %1;" :: "r"(a), "r"(tx) : "memory");
}
__device__ __forceinline__ void mbar_wait(uint32_t a, uint32_t ph) {
    asm volatile(
        "{\n\t.reg .pred P;\n"
        "WL%=:\n\t"
        "mbarrier.try_wait.parity.shared.b64 P, [%0], %1, 0x989680;\n\t"
        "@P bra WD%=;\n\t"
        "bra WL%=;\n"
        "WD%=:\n\t}"
        :: "r"(a), "r"(ph) : "memory");
}
__device__ __forceinline__ void bulkcp(uint32_t d, const void* s, uint32_t n, uint32_t mb) {
    asm volatile(
        "cp.async.bulk.shared::cluster.global.mbarrier::complete_tx::bytes [%0], [%1], %2, [%3];"
        :: "r"(d), "l"(s), "r"(n), "r"(mb) : "memory");
}
__device__ __forceinline__ void ldsm4(uint32_t r[4], uint32_t saddr) {
    asm volatile("ldmatrix.sync.aligned.m8n8.x4.shared.b16 {%0,%1,%2,%3}, [%4];"
        : "=r"(r[0]), "=r"(r[1]), "=r"(r[2]), "=r"(r[3]) : "r"(saddr));
}
__device__ __forceinline__ void mma16(float c[4], const uint32_t a[4], const uint32_t b[2]) {
    asm volatile(
        "mma.sync.aligned.m16n8k16.row.col.f32.f16.f16.f32 "
        "{%0,%1,%2,%3},{%4,%5,%6,%7},{%8,%9},{%0,%1,%2,%3};\n"
        : "+f"(c[0]), "+f"(c[1]), "+f"(c[2]), "+f"(c[3])
        : "r"(a[0]), "r"(a[1]), "r"(a[2]), "r"(a[3]), "r"(b[0]), "r"(b[1]));
}

// ---------------- fused GEMM(+update) CTA-unit ----------------
// C[256, NT] = A0[256,4096] @ W0p^T (+ tiles t>=64: A1 @ W1p^T). Panels pre-swizzled.
// 256 threads = 8 warps, single domain. Warp tile (MI*16) x (NI*8).
// MI=4: warps 4x2 (64x32 tiles).  MI=2: warps 8x1 (32x32 tiles). 2-stage ring.
template <int NT, int MI, bool RAW>
__device__ __forceinline__ void gemm_unit(
    char* dsm, int nTiles,
    const __half* __restrict__ A0, const __half* __restrict__ W0p,
    const __half* __restrict__ A1, const __half* __restrict__ W1p,
    int nBase,
    const float* __restrict__ oldS, float* __restrict__ newSf,
    __half* __restrict__ newShPan, const float* __restrict__ bias,
    const float* __restrict__ topP, float* __restrict__ rawOut)
{
    constexpr int WM  = 16 / MI;                 // warps along M (4 or 8)
    constexpr int WNc = 8 / WM;                  // warps along N (2 or 1)
    constexpr int NI  = NT / (8 * WNc);          // n8 tiles per warp (=4 both configs)
    constexpr int STB = 32768 + NT * 128;        // stage bytes
    constexpr uint32_t TXB = (uint32_t)STB;

    __shared__ uint64_t mbF[2], mbE[2];

    const int tid   = threadIdx.x;
    const int warp  = tid >> 5;
    const int lane  = tid & 31;
    const int lq    = lane >> 2;
    const int lr    = lane & 3;
    const int warpM = warp % WM;
    const int warpN = warp / WM;

    const uint32_t sm_b  = s2u(dsm);
    const uint32_t mbF_b = s2u(&mbF[0]);
    const uint32_t mbE_b = s2u(&mbE[0]);

    if (tid == 0) {
        #pragma unroll
        for (int s = 0; s < 2; s++) {
            mbar_init(mbF_b + 8 * s, 1);         // tx-tracked fill
            mbar_init(mbE_b + 8 * s, 8);         // 8 consumer warps
        }
    }
    __syncthreads();

    const bool prod = (tid == 0);

    auto issue = [&](int s, int t) {             // producer thread only
        const __half* A = (t < 64) ? A0 : A1;
        const __half* W = (t < 64) ? W0p : W1p;
        const int tt = t & 63;
        const uint32_t mb = mbF_b + 8 * s;
        const uint32_t d  = sm_b + s * STB;
        mbar_expect(mb, TXB);
        bulkcp(d, A + (size_t)tt * (256 * 64), 32768, mb);           // A: 256 rows
        bulkcp(d + 32768, W + (size_t)tt * (NT * 64), NT * 128, mb); // W: NT rows
    };

    if (prod) { issue(0, 0); issue(1, 1); }

    // fragment addressing (W region at +32768)
    const int msk = lane & 7;
    const int aKh = lane >> 4;
    const int bKh = (lane >> 3) & 1;
    int aByte[MI];
    #pragma unroll
    for (int mi = 0; mi < MI; mi++) {
        int row = warpM * (MI * 16) + mi * 16 + (lane & 7) + 8 * ((lane >> 3) & 1);
        aByte[mi] = row * 128;
    }
    int bByte[NI / 2];
    #pragma unroll
    for (int j = 0; j < NI / 2; j++) {
        int row = warpN * (NI * 8) + j * 16 + (lane & 7) + 8 * (lane >> 4);
        bByte[j] = 32768 + row * 128;
    }
    uint32_t aCh[4], bCh[4];                     // per-ks swizzled chunk offsets
    #pragma unroll
    for (int ks = 0; ks < 4; ks++) {
        aCh[ks] = (uint32_t)(((2 * ks + aKh) ^ msk) << 4);
        bCh[ks] = (uint32_t)(((2 * ks + bKh) ^ msk) << 4);
    }

    float acc[MI][NI][4];
    #pragma unroll
    for (int mi = 0; mi < MI; mi++)
        #pragma unroll
        for (int ni = 0; ni < NI; ni++)
            #pragma unroll
            for (int f = 0; f < 4; f++) acc[mi][ni][f] = 0.0f;

    uint32_t afr[2][MI][4];
    uint32_t bfr[2][NI / 2][4];
    auto load_frag = [&](uint32_t stB, int ks, int pb) {
        #pragma unroll
        for (int mi = 0; mi < MI; mi++)
            ldsm4(afr[pb][mi], stB + aByte[mi] + aCh[ks]);
        #pragma unroll
        for (int j = 0; j < NI / 2; j++)
            ldsm4(bfr[pb][j], stB + bByte[j] + bCh[ks]);
    };

    for (int t = 0; t < nTiles; t++) {
        const int s = t & 1;
        const uint32_t ph = (uint32_t)((t >> 1) & 1);
        mbar_wait(mbF_b + 8 * s, ph);

        const uint32_t stB = sm_b + (uint32_t)(s * STB);
        load_frag(stB, 0, 0);
        #pragma unroll
        for (int ks = 0; ks < 4; ks++) {
            const int pb = ks & 1;
            if (ks < 3) load_frag(stB, ks + 1, pb ^ 1);
            #pragma unroll
            for (int mi = 0; mi < MI; mi++)
                #pragma unroll
                for (int ni = 0; ni < NI; ni++)
                    mma16(acc[mi][ni], afr[pb][mi], &bfr[pb][ni >> 1][(ni & 1) * 2]);
        }

        if (lane == 0) mbar_arrive(mbE_b + 8 * s);
        if (prod && t + 2 < nTiles) {
            mbar_wait(mbE_b + 8 * s, ph);        // all 8 warps done with stage s
            issue(s, t + 2);
        }
    }

    // ---- fused epilogue (each output element owned by this block) ----
    #pragma unroll
    for (int mi = 0; mi < MI; mi++) {
        #pragma unroll
        for (int ni = 0; ni < NI; ni++) {
            int r = warpM * (MI * 16) + mi * 16 + lq;
            int c0 = nBase + warpN * (NI * 8) + ni * 8 + 2 * lr;
            #pragma unroll
            for (int h = 0; h < 2; h++) {
                int rr = r + 8 * h;
                float y0 = acc[mi][ni][2 * h + 0];
                float y1 = acc[mi][ni][2 * h + 1];
                size_t idx = (size_t)rr * DIM + c0;
                if (RAW) {
                    *(float2*)(rawOut + idx) = make_float2(y0, y1);
                } else {
                    y0 += bias[c0];
                    y1 += bias[c0 + 1];
                    if (topP) { y0 += topP[idx]; y1 += topP[idx + 1]; }
                    float n0 = fminf(fmaxf(0.5f * oldS[idx]     + 0.5f * y0, 0.0f), 1.0f);
                    float n1 = fminf(fmaxf(0.5f * oldS[idx + 1] + 0.5f * y1, 0.0f), 1.0f);
                    *(float2*)(newSf + idx) = make_float2(n0, n1);
                    // packed-swizzled panel write for next step's bulk loads
                    uint32_t off = (uint32_t)(((c0 >> 6) * 256 + rr) * 64
                                   + ((((c0 & 63) >> 3) ^ (rr & 7)) * 8) + (c0 & 7));
                    *(__half2*)(newShPan + off) = __floats2half2_rn(n0, n1);
                }
            }
        }
    }
}

// -------- one relaxation step: 256 equal-work CTAs, 2 co-resident per SM --------
__global__ void __launch_bounds__(256, 2) step_kernel(
    int p, const float* __restrict__ b0, const float* __restrict__ b2,
    const float* __restrict__ b4)
{
    extern __shared__ __align__(1024) char dsm[];
    const int bid = blockIdx.x;
    const int q = p ^ 1;
    if (bid < 64) {                 // s0' <- clip(.5 s0 + .5 (s1 @ W0^T + b0))
        const int nB = bid * 64;
        gemm_unit<64, 4, false>(dsm, 64, g_sh[p][1], gW0 + (size_t)nB * DIM,
                                g_sh[p][1], gW0 + (size_t)nB * DIM, nB,
                                g_sf[p][0], g_sf[q][0], g_sh[q][0], b0, nullptr, nullptr);
    } else if (bid < 192) {         // s1' <- clip(.5 s1 + .5 (s2 @ W2^T + s0 @ W1^T + b2))
        const int nB = (bid - 64) * 32;
        gemm_unit<32, 2, false>(dsm, 128, g_sh[p][2], gW2 + (size_t)nB * DIM,
                                g_sh[p][0], gW1 + (size_t)nB * DIM, nB,
                                g_sf[p][1], g_sf[q][1], g_sh[q][1], b2, nullptr, nullptr);
    } else {                        // s2' <- clip(.5 s2 + .5 (s1 @ W3^T + top + b4))
        const int nB = (bid - 192) * 64;
        gemm_unit<64, 4, false>(dsm, 64, g_sh[p][1], gW3 + (size_t)nB * DIM,
                                g_sh[p][1], gW3 + (size_t)nB * DIM, nB,
                                g_sf[p][2], g_sf[q][2], g_sh[q][2], b4, g_top, nullptr);
    }
}

__global__ void __launch_bounds__(256, 2) top_kernel()
{
    extern __shared__ __align__(1024) char dsm[];
    const int nB = blockIdx.x * 32;
    gemm_unit<32, 2, true>(dsm, 64, g_s3h, gW4 + (size_t)nB * DIM,
                           g_s3h, gW4 + (size_t)nB * DIM, nB,
                           nullptr, nullptr, nullptr, nullptr, nullptr, g_top);
}

// -------- setup: pack + swizzle weights and state --------
__global__ void wconv_kernel(const float* __restrict__ w0, const float* __restrict__ w1,
                             const float* __restrict__ w2, const float* __restrict__ w3,
                             const float* __restrict__ w4)
{
    const float* src;
    __half* dst;
    int ntShift;                       // log2(NTp)
    switch (blockIdx.y) {
        case 0: src = w0; dst = gW0; ntShift = 6; break;
        case 1: src = w1; dst = gW1; ntShift = 5; break;
        case 2: src = w2; dst = gW2; ntShift = 5; break;
        case 3: src = w3; dst = gW3; ntShift = 6; break;
        default: src = w4; dst = gW4; ntShift = 5; break;
    }
    const int id = blockIdx.x * blockDim.x + threadIdx.x;   // 0 .. 2M-1 (16B chunks)
    const int n  = id >> 9;
    const int kc = id & 511;
    float4 v0 = *(const float4*)(src + (size_t)n * DIM + kc * 8);
    float4 v1 = *(const float4*)(src + (size_t)n * DIM + kc * 8 + 4);
    __half2 h[4] = { __floats2half2_rn(v0.x, v0.y), __floats2half2_rn(v0.z, v0.w),
                     __floats2half2_rn(v1.x, v1.y), __floats2half2_rn(v1.z, v1.w) };
    const int NTp = 1 << ntShift;
    const int row = n & (NTp - 1);
    const int nT  = n >> ntShift;
    const int kT  = kc >> 3;
    const int ch  = kc & 7;
    size_t off = ((size_t)(nT * 64 + kT) * NTp + row) * 64 + (size_t)((ch ^ (row & 7)) * 8);
    *(uint4*)(dst + off) = *(uint4*)h;
}

__global__ void init_kernel(const float* __restrict__ s0, const float* __restrict__ s1,
                            const float* __restrict__ s2, const float* __restrict__ s3)
{
    const int layer = blockIdx.y;      // 0..3 (3 = s3)
    const float* src = (layer == 0) ? s0 : (layer == 1) ? s1 : (layer == 2) ? s2 : s3;
    __half* pan = (layer == 3) ? g_s3h : g_sh[0][layer];
    const int id = blockIdx.x * blockDim.x + threadIdx.x;   // 0 .. BD/8-1
    const int row = id >> 9;
    const int kc  = id & 511;
    float4 v0 = *(const float4*)(src + (size_t)row * DIM + kc * 8);
    float4 v1 = *(const float4*)(src + (size_t)row * DIM + kc * 8 + 4);
    __half2 h[4] = { __floats2half2_rn(v0.x, v0.y), __floats2half2_rn(v0.z, v0.w),
                     __floats2half2_rn(v1.x, v1.y), __floats2half2_rn(v1.z, v1.w) };
    size_t off = ((size_t)(kc >> 3) * 256 + row) * 64 + (size_t)(((kc & 7) ^ (row & 7)) * 8);
    *(uint4*)(pan + off) = *(uint4*)h;
    if (layer < 3) {
        float* sf = g_sf[0][layer] + (size_t)row * DIM + kc * 8;
        *(float4*)sf = v0;
        *(float4*)(sf + 4) = v1;
    }
}

__global__ void out_kernel(float* __restrict__ out)
{
    int i = blockIdx.x * blockDim.x + threadIdx.x;
    out[i]          = g_sf[0][0][i];
    out[BD + i]     = g_sf[0][1][i];
    out[2 * BD + i] = g_sf[0][2][i];
}

extern "C" void kernel_launch(void* const* d_in, const int* in_sizes, int n_in,
                              void* d_out, int out_size)
{
    const float* s0 = (const float*)d_in[0];
    const float* s1 = (const float*)d_in[1];
    const float* s2 = (const float*)d_in[2];
    const float* s3 = (const float*)d_in[3];
    const float* W0 = (const float*)d_in[4];
    const float* b0 = (const float*)d_in[5];
    const float* W1 = (const float*)d_in[6];
    const float* W2 = (const float*)d_in[7];
    const float* b2 = (const float*)d_in[8];
    const float* W3 = (const float*)d_in[9];
    const float* W4 = (const float*)d_in[10];
    const float* b4 = (const float*)d_in[11];

    static_assert(2 * SMEM_BYTES <= 227 * 1024, "2-CTA smem budget");
    cudaFuncSetAttribute(step_kernel, cudaFuncAttributeMaxDynamicSharedMemorySize, SMEM_BYTES);
    cudaFuncSetAttribute(top_kernel,  cudaFuncAttributeMaxDynamicSharedMemorySize, SMEM_BYTES);

    wconv_kernel<<<dim3(DIM * DIM / 8 / 256, 5), 256>>>(W0, W1, W2, W3, W4);
    init_kernel<<<dim3(BD / 8 / 256, 4), 256>>>(s0, s1, s2, s3);

    top_kernel<<<128, 256, SMEM_BYTES>>>();

    for (int t = 0; t < NSTEPS; t++)
        step_kernel<<<256, 256, SMEM_BYTES>>>(t & 1, b0, b2, b4);

    out_kernel<<<BD / 256, 256>>>((float*)d_out);
}

// round 15
// speedup vs baseline: 1.1466x; 1.1466x over previous
#include <cuda_runtime.h>
#include <cuda_fp16.h>
#include <cstdint>

#define BATCH  256
#define DIM    4096
#define BD     (BATCH * DIM)
#define NSTEPS 30
#define SMEM_BYTES 196608   // 2 halves x (3 x 32KB | 4 x 24KB | 4 x 20KB)

// ---------------- persistent device scratch (packed, pre-swizzled) ----------------
// Weights: [N/NTp][64 kTiles][NTp rows][64 halfs], chunk c of row stored at c^(row&7)
__device__ __align__(128) __half gW0[(size_t)DIM * DIM];   // NTp=128
__device__ __align__(128) __half gW1[(size_t)DIM * DIM];   // NTp=64
__device__ __align__(128) __half gW2[(size_t)DIM * DIM];   // NTp=64
__device__ __align__(128) __half gW3[(size_t)DIM * DIM];   // NTp=128
__device__ __align__(128) __half gW4[(size_t)DIM * DIM];   // NTp=32 (wide top grid)
__device__ float g_sf[2][3][BD];                            // fp32 state (plain)
__device__ __align__(128) __half g_sh[2][3][BD];            // f16 state, panel-packed [64][256][64]
__device__ __align__(128) __half g_s3h[BD];                 // f16 data layer, panel-packed
__device__ float g_top[BD];                                 // s3 @ W4^T (plain fp32)

// ---------------- helpers ----------------
__device__ __forceinline__ uint32_t s2u(const void* p) {
    return (uint32_t)__cvta_generic_to_shared(p);
}
__device__ __forceinline__ void mbar_init(uint32_t a, uint32_t c) {
    asm volatile("mbarrier.init.shared.b64 [%0], %1;" :: "r"(a), "r"(c) : "memory");
}
__device__ __forceinline__ void mbar_arrive(uint32_t a) {
    asm volatile("mbarrier.arrive.shared.b64 _, [%0];" :: "r"(a) : "memory");
}
__device__ __forceinline__ void mbar_expect(uint32_t a, uint32_t tx) {
    asm volatile("mbarrier.arrive.expect_tx.shared.b64 _, [%0], %1;" :: "r"(a), "r"(tx) : "memory");
}
__device__ __forceinline__ void mbar_wait(uint32_t a, uint32_t ph) {
    asm volatile(
        "{\n\t.reg .pred P;\n"
        "WL%=:\n\t"
        "mbarrier.try_wait.parity.shared.b64 P, [%0], %1, 0x989680;\n\t"
        "@P bra WD%=;\n\t"
        "bra WL%=;\n"
        "WD%=:\n\t}"
        :: "r"(a), "r"(ph) : "memory");
}
__device__ __forceinline__ void bulkcp(uint32_t d, const void* s, uint32_t n, uint32_t mb) {
    asm volatile(
        "cp.async.bulk.shared::cluster.global.mbarrier::complete_tx::bytes [%0], [%1], %2, [%3];"
        :: "r"(d), "l"(s), "r"(n), "r"(mb) : "memory");
}
__device__ __forceinline__ void ldsm4(uint32_t r[4], uint32_t saddr) {
    asm volatile("ldmatrix.sync.aligned.m8n8.x4.shared.b16 {%0,%1,%2,%3}, [%4];"
        : "=r"(r[0]), "=r"(r[1]), "=r"(r[2]), "=r"(r[3]) : "r"(saddr));
}
__device__ __forceinline__ void mma16(float c[4], const uint32_t a[4], const uint32_t b[2]) {
    asm volatile(
        "mma.sync.aligned.m16n8k16.row.col.f32.f16.f16.f32 "
        "{%0,%1,%2,%3},{%4,%5,%6,%7},{%8,%9},{%0,%1,%2,%3};\n"
        : "+f"(c[0]), "+f"(c[1]), "+f"(c[2]), "+f"(c[3])
        : "r"(a[0]), "r"(a[1]), "r"(a[2]), "r"(a[3]), "r"(b[0]), "r"(b[1]));
}

// ---------------- fused GEMM(+update) block-unit, 2 independent halves ----------------
// C[256, NT] = A0[256,4096] @ W0p^T (+ tiles t>=64: A1 @ W1p^T). Panels pre-swizzled.
// 512 threads = 2 halves x 8 warps. Half h owns rows [h*128, h*128+128).
// Warp tile 32 x (NT/2).  Ring: 3 stages for NT=128, 4 otherwise.
template <int NT, bool RAW>
__device__ __forceinline__ void gemm_unit(
    char* dsm, int nTiles,
    const __half* __restrict__ A0, const __half* __restrict__ W0p,
    const __half* __restrict__ A1, const __half* __restrict__ W1p,
    int nBase,
    const float* __restrict__ oldS, float* __restrict__ newSf,
    __half* __restrict__ newShPan, const float* __restrict__ bias,
    const float* __restrict__ topP, float* __restrict__ rawOut)
{
    constexpr int NI   = NT / 16;                // n8 tiles per warp (8, 4 or 2)
    constexpr int HSB  = 16384 + NT * 128;       // stage bytes per half
    constexpr int NSTG = (NT == 128) ? 3 : 4;    // ring depth per half
    constexpr uint32_t TXB = (uint32_t)HSB;

    __shared__ uint64_t mbF[2][4], mbE[2][4];

    const int tid   = threadIdx.x;
    const int warp  = tid >> 5;
    const int lane  = tid & 31;
    const int half  = warp >> 3;
    const int hwarp = warp & 7;
    const int lq    = lane >> 2;
    const int lr    = lane & 3;
    const int warpM = hwarp >> 1;                // 0..3 (32-row tiles)
    const int warpN = hwarp & 1;

    const uint32_t smH_b = s2u(dsm) + half * (NSTG * HSB);
    const uint32_t mbF_b = s2u(&mbF[half][0]);
    const uint32_t mbE_b = s2u(&mbE[half][0]);

    if (tid == 0) {
        #pragma unroll
        for (int h = 0; h < 2; h++)
            #pragma unroll
            for (int s = 0; s < NSTG; s++) {
                mbar_init(s2u(&mbF[h][s]), 1);   // tx-tracked fill
                mbar_init(s2u(&mbE[h][s]), 8);   // 8 consumer warps per half
            }
    }
    __syncthreads();

    const bool prod = (hwarp == 0 && lane == 0);

    auto issue = [&](int s, int t) {             // producer thread only
        const __half* A = (t < 64) ? A0 : A1;
        const __half* W = (t < 64) ? W0p : W1p;
        const int tt = t & 63;
        const uint32_t mb = mbF_b + 8 * s;
        const uint32_t dA = smH_b + s * HSB;
        mbar_expect(mb, TXB);
        bulkcp(dA, A + (size_t)(tt * 256 + half * 128) * 64, 16384, mb);
        bulkcp(dA + 16384, W + (size_t)tt * (NT * 64), NT * 128, mb);
    };

    if (prod) {
        #pragma unroll
        for (int s = 0; s < NSTG; s++) issue(s, s);
    }

    // fragment addressing (rows local to half; W region at +16384)
    const int msk = lane & 7;
    const int aKh = lane >> 4;
    const int bKh = (lane >> 3) & 1;
    int aByte[2];
    #pragma unroll
    for (int mi = 0; mi < 2; mi++) {
        int row = warpM * 32 + mi * 16 + (lane & 7) + 8 * ((lane >> 3) & 1);
        aByte[mi] = row * 128;
    }
    int bByte[NI / 2];
    #pragma unroll
    for (int j = 0; j < NI / 2; j++) {
        int row = 128 + warpN * (NI * 8) + j * 16 + (lane & 7) + 8 * (lane >> 4);
        bByte[j] = row * 128;
    }
    uint32_t aCh[4], bCh[4];                     // per-ks swizzled chunk offsets
    #pragma unroll
    for (int ks = 0; ks < 4; ks++) {
        aCh[ks] = (uint32_t)(((2 * ks + aKh) ^ msk) << 4);
        bCh[ks] = (uint32_t)(((2 * ks + bKh) ^ msk) << 4);
    }

    float acc[2][NI][4];
    #pragma unroll
    for (int mi = 0; mi < 2; mi++)
        #pragma unroll
        for (int ni = 0; ni < NI; ni++)
            #pragma unroll
            for (int f = 0; f < 4; f++) acc[mi][ni][f] = 0.0f;

    uint32_t afr[2][2][4];
    uint32_t bfr[2][NI / 2][4];
    auto load_frag = [&](uint32_t stB, int ks, int pb) {
        #pragma unroll
        for (int mi = 0; mi < 2; mi++)
            ldsm4(afr[pb][mi], stB + aByte[mi] + aCh[ks]);
        #pragma unroll
        for (int j = 0; j < NI / 2; j++)
            ldsm4(bfr[pb][j], stB + bByte[j] + bCh[ks]);
    };

    int st = 0;
    uint32_t ph = 0;
    for (int t = 0; t < nTiles; t++) {
        mbar_wait(mbF_b + 8 * st, ph);

        const uint32_t stB = smH_b + (uint32_t)(st * HSB);
        load_frag(stB, 0, 0);
        #pragma unroll
        for (int ks = 0; ks < 4; ks++) {
            const int pb = ks & 1;
            if (ks < 3) load_frag(stB, ks + 1, pb ^ 1);
            #pragma unroll
            for (int mi = 0; mi < 2; mi++)
                #pragma unroll
                for (int ni = 0; ni < NI; ni++)
                    mma16(acc[mi][ni], afr[pb][mi], &bfr[pb][ni >> 1][(ni & 1) * 2]);
        }

        if (lane == 0) mbar_arrive(mbE_b + 8 * st);
        if (prod && t + NSTG < nTiles) {
            mbar_wait(mbE_b + 8 * st, ph);       // all 8 warps done with stage st
            issue(st, t + NSTG);
        }
        if (++st == NSTG) { st = 0; ph ^= 1; }
    }

    // ---- fused epilogue (each output element owned by this block) ----
    #pragma unroll
    for (int mi = 0; mi < 2; mi++) {
        #pragma unroll
        for (int ni = 0; ni < NI; ni++) {
            int r = half * 128 + warpM * 32 + mi * 16 + lq;
            int c0 = nBase + warpN * (NI * 8) + ni * 8 + 2 * lr;
            #pragma unroll
            for (int h = 0; h < 2; h++) {
                int rr = r + 8 * h;
                float y0 = acc[mi][ni][2 * h + 0];
                float y1 = acc[mi][ni][2 * h + 1];
                size_t idx = (size_t)rr * DIM + c0;
                if (RAW) {
                    *(float2*)(rawOut + idx) = make_float2(y0, y1);
                } else {
                    y0 += bias[c0];
                    y1 += bias[c0 + 1];
                    if (topP) { y0 += topP[idx]; y1 += topP[idx + 1]; }
                    float n0 = fminf(fmaxf(0.5f * oldS[idx]     + 0.5f * y0, 0.0f), 1.0f);
                    float n1 = fminf(fmaxf(0.5f * oldS[idx + 1] + 0.5f * y1, 0.0f), 1.0f);
                    *(float2*)(newSf + idx) = make_float2(n0, n1);
                    // packed-swizzled panel write for next step's bulk loads
                    uint32_t off = (uint32_t)(((c0 >> 6) * 256 + rr) * 64
                                   + ((((c0 & 63) >> 3) ^ (rr & 7)) * 8) + (c0 & 7));
                    *(__half2*)(newShPan + off) = __floats2half2_rn(n0, n1);
                }
            }
        }
    }
}

// -------- one relaxation step: 128 equal-work blocks, one wave --------
__global__ void __launch_bounds__(512, 1) step_kernel(
    int p, const float* __restrict__ b0, const float* __restrict__ b2,
    const float* __restrict__ b4)
{
    extern __shared__ __align__(1024) char dsm[];
    const int bid = blockIdx.x;
    const int q = p ^ 1;
    if (bid < 32) {                 // s0' <- clip(.5 s0 + .5 (s1 @ W0^T + b0))
        const int nB = bid * 128;
        gemm_unit<128, false>(dsm, 64, g_sh[p][1], gW0 + (size_t)nB * DIM,
                              g_sh[p][1], gW0 + (size_t)nB * DIM, nB,
                              g_sf[p][0], g_sf[q][0], g_sh[q][0], b0, nullptr, nullptr);
    } else if (bid < 96) {          // s1' <- clip(.5 s1 + .5 (s2 @ W2^T + s0 @ W1^T + b2))
        const int nB = (bid - 32) * 64;
        gemm_unit<64, false>(dsm, 128, g_sh[p][2], gW2 + (size_t)nB * DIM,
                             g_sh[p][0], gW1 + (size_t)nB * DIM, nB,
                             g_sf[p][1], g_sf[q][1], g_sh[q][1], b2, nullptr, nullptr);
    } else {                        // s2' <- clip(.5 s2 + .5 (s1 @ W3^T + top + b4))
        const int nB = (bid - 96) * 128;
        gemm_unit<128, false>(dsm, 64, g_sh[p][1], gW3 + (size_t)nB * DIM,
                              g_sh[p][1], gW3 + (size_t)nB * DIM, nB,
                              g_sf[p][2], g_sf[q][2], g_sh[q][2], b4, g_top, nullptr);
    }
}

// top = s3 @ W4^T over 128 blocks of N=32 (one wave, ~4x shorter critical path)
__global__ void __launch_bounds__(512, 1) top_kernel()
{
    extern __shared__ __align__(1024) char dsm[];
    const int nB = blockIdx.x * 32;
    gemm_unit<32, true>(dsm, 64, g_s3h, gW4 + (size_t)nB * DIM,
                        g_s3h, gW4 + (size_t)nB * DIM, nB,
                        nullptr, nullptr, nullptr, nullptr, nullptr, g_top);
}

// -------- setup: pack + swizzle weights and state --------
__global__ void wconv_kernel(const float* __restrict__ w0, const float* __restrict__ w1,
                             const float* __restrict__ w2, const float* __restrict__ w3,
                             const float* __restrict__ w4)
{
    const float* src;
    __half* dst;
    int ntShift;                       // log2(NTp)
    switch (blockIdx.y) {
        case 0: src = w0; dst = gW0; ntShift = 7; break;
        case 1: src = w1; dst = gW1; ntShift = 6; break;
        case 2: src = w2; dst = gW2; ntShift = 6; break;
        case 3: src = w3; dst = gW3; ntShift = 7; break;
        default: src = w4; dst = gW4; ntShift = 5; break;
    }
    const int id = blockIdx.x * blockDim.x + threadIdx.x;   // 0 .. 2M-1 (16B chunks)
    const int n  = id >> 9;
    const int kc = id & 511;
    float4 v0 = *(const float4*)(src + (size_t)n * DIM + kc * 8);
    float4 v1 = *(const float4*)(src + (size_t)n * DIM + kc * 8 + 4);
    __half2 h[4] = { __floats2half2_rn(v0.x, v0.y), __floats2half2_rn(v0.z, v0.w),
                     __floats2half2_rn(v1.x, v1.y), __floats2half2_rn(v1.z, v1.w) };
    const int NTp = 1 << ntShift;
    const int row = n & (NTp - 1);
    const int nT  = n >> ntShift;
    const int kT  = kc >> 3;
    const int ch  = kc & 7;
    size_t off = ((size_t)(nT * 64 + kT) * NTp + row) * 64 + (size_t)((ch ^ (row & 7)) * 8);
    *(uint4*)(dst + off) = *(uint4*)h;
}

__global__ void init_kernel(const float* __restrict__ s0, const float* __restrict__ s1,
                            const float* __restrict__ s2, const float* __restrict__ s3)
{
    const int layer = blockIdx.y;      // 0..3 (3 = s3)
    const float* src = (layer == 0) ? s0 : (layer == 1) ? s1 : (layer == 2) ? s2 : s3;
    __half* pan = (layer == 3) ? g_s3h : g_sh[0][layer];
    const int id = blockIdx.x * blockDim.x + threadIdx.x;   // 0 .. BD/8-1
    const int row = id >> 9;
    const int kc  = id & 511;
    float4 v0 = *(const float4*)(src + (size_t)row * DIM + kc * 8);
    float4 v1 = *(const float4*)(src + (size_t)row * DIM + kc * 8 + 4);
    __half2 h[4] = { __floats2half2_rn(v0.x, v0.y), __floats2half2_rn(v0.z, v0.w),
                     __floats2half2_rn(v1.x, v1.y), __floats2half2_rn(v1.z, v1.w) };
    size_t off = ((size_t)(kc >> 3) * 256 + row) * 64 + (size_t)(((kc & 7) ^ (row & 7)) * 8);
    *(uint4*)(pan + off) = *(uint4*)h;
    if (layer < 3) {
        float* sf = g_sf[0][layer] + (size_t)row * DIM + kc * 8;
        *(float4*)sf = v0;
        *(float4*)(sf + 4) = v1;
    }
}

__global__ void out_kernel(float* __restrict__ out)
{
    int i = blockIdx.x * blockDim.x + threadIdx.x;
    out[i]          = g_sf[0][0][i];
    out[BD + i]     = g_sf[0][1][i];
    out[2 * BD + i] = g_sf[0][2][i];
}

extern "C" void kernel_launch(void* const* d_in, const int* in_sizes, int n_in,
                              void* d_out, int out_size)
{
    const float* s0 = (const float*)d_in[0];
    const float* s1 = (const float*)d_in[1];
    const float* s2 = (const float*)d_in[2];
    const float* s3 = (const float*)d_in[3];
    const float* W0 = (const float*)d_in[4];
    const float* b0 = (const float*)d_in[5];
    const float* W1 = (const float*)d_in[6];
    const float* W2 = (const float*)d_in[7];
    const float* b2 = (const float*)d_in[8];
    const float* W3 = (const float*)d_in[9];
    const float* W4 = (const float*)d_in[10];
    const float* b4 = (const float*)d_in[11];

    static_assert(SMEM_BYTES <= 227 * 1024, "smem budget");
    cudaFuncSetAttribute(step_kernel, cudaFuncAttributeMaxDynamicSharedMemorySize, SMEM_BYTES);
    cudaFuncSetAttribute(top_kernel,  cudaFuncAttributeMaxDynamicSharedMemorySize, SMEM_BYTES);

    wconv_kernel<<<dim3(DIM * DIM / 8 / 256, 5), 256>>>(W0, W1, W2, W3, W4);
    init_kernel<<<dim3(BD / 8 / 256, 4), 256>>>(s0, s1, s2, s3);

    top_kernel<<<128, 512, SMEM_BYTES>>>();

    for (int t = 0; t < NSTEPS; t++)
        step_kernel<<<128, 512, SMEM_BYTES>>>(t & 1, b0, b2, b4);

    out_kernel<<<BD / 256, 256>>>((float*)d_out);
}

// round 16
// speedup vs baseline: 1.1698x; 1.0202x over previous
#include <cuda_runtime.h>
#include <cuda_fp16.h>
#include <cstdint>

#define BATCH  256
#define DIM    4096
#define BD     (BATCH * DIM)
#define NSTEPS 30
#define SMEM_BYTES 196608   // 2 halves x (3 x 32KB | 4 x 24KB | 4 x 20KB)

// ---------------- persistent device scratch (packed, pre-swizzled) ----------------
// Weights: [N/NTp][64 kTiles][NTp rows][64 halfs], chunk c of row stored at c^(row&7)
__device__ __align__(128) __half gW0[(size_t)DIM * DIM];   // NTp=128
__device__ __align__(128) __half gW1[(size_t)DIM * DIM];   // NTp=64
__device__ __align__(128) __half gW2[(size_t)DIM * DIM];   // NTp=64
__device__ __align__(128) __half gW3[(size_t)DIM * DIM];   // NTp=128
__device__ __align__(128) __half gW4[(size_t)DIM * DIM];   // NTp=32 (wide top grid)
__device__ __align__(128) __half g_sh[2][3][BD];            // f16 state, panel-packed [64][256][64]
__device__ __align__(128) __half g_s3h[BD];                 // f16 data layer, panel-packed
__device__ float g_top[BD];                                 // s3 @ W4^T (fp32: avoids bias)

// ---------------- helpers ----------------
__device__ __forceinline__ uint32_t s2u(const void* p) {
    return (uint32_t)__cvta_generic_to_shared(p);
}
__device__ __forceinline__ void mbar_init(uint32_t a, uint32_t c) {
    asm volatile("mbarrier.init.shared.b64 [%0], %1;" :: "r"(a), "r"(c) : "memory");
}
__device__ __forceinline__ void mbar_arrive(uint32_t a) {
    asm volatile("mbarrier.arrive.shared.b64 _, [%0];" :: "r"(a) : "memory");
}
__device__ __forceinline__ void mbar_expect(uint32_t a, uint32_t tx) {
    asm volatile("mbarrier.arrive.expect_tx.shared.b64 _, [%0], %1;" :: "r"(a), "r"(tx) : "memory");
}
__device__ __forceinline__ void mbar_wait(uint32_t a, uint32_t ph) {
    asm volatile(
        "{\n\t.reg .pred P;\n"
        "WL%=:\n\t"
        "mbarrier.try_wait.parity.shared.b64 P, [%0], %1, 0x989680;\n\t"
        "@P bra WD%=;\n\t"
        "bra WL%=;\n"
        "WD%=:\n\t}"
        :: "r"(a), "r"(ph) : "memory");
}
__device__ __forceinline__ void bulkcp(uint32_t d, const void* s, uint32_t n, uint32_t mb) {
    asm volatile(
        "cp.async.bulk.shared::cluster.global.mbarrier::complete_tx::bytes [%0], [%1], %2, [%3];"
        :: "r"(d), "l"(s), "r"(n), "r"(mb) : "memory");
}
__device__ __forceinline__ void ldsm4(uint32_t r[4], uint32_t saddr) {
    asm volatile("ldmatrix.sync.aligned.m8n8.x4.shared.b16 {%0,%1,%2,%3}, [%4];"
        : "=r"(r[0]), "=r"(r[1]), "=r"(r[2]), "=r"(r[3]) : "r"(saddr));
}
__device__ __forceinline__ void mma16(float c[4], const uint32_t a[4], const uint32_t b[2]) {
    asm volatile(
        "mma.sync.aligned.m16n8k16.row.col.f32.f16.f16.f32 "
        "{%0,%1,%2,%3},{%4,%5,%6,%7},{%8,%9},{%0,%1,%2,%3};\n"
        : "+f"(c[0]), "+f"(c[1]), "+f"(c[2]), "+f"(c[3])
        : "r"(a[0]), "r"(a[1]), "r"(a[2]), "r"(a[3]), "r"(b[0]), "r"(b[1]));
}

// ---------------- fused GEMM(+update) block-unit, 2 independent halves ----------------
// C[256, NT] = A0[256,4096] @ W0p^T (+ tiles t>=64: A1 @ W1p^T). Panels pre-swizzled.
// 512 threads = 2 halves x 8 warps. Half h owns rows [h*128, h*128+128).
// Warp tile 32 x (NT/2).  Ring: 3 stages for NT=128, 4 otherwise.
// State is fp16-panel only: epilogue reads oldPan, writes newPan (no fp32 mirror).
template <int NT, bool RAW>
__device__ __forceinline__ void gemm_unit(
    char* dsm, int nTiles,
    const __half* __restrict__ A0, const __half* __restrict__ W0p,
    const __half* __restrict__ A1, const __half* __restrict__ W1p,
    int nBase,
    const __half* __restrict__ oldPan, __half* __restrict__ newPan,
    const float* __restrict__ bias,
    const float* __restrict__ topP, float* __restrict__ rawOut)
{
    constexpr int NI   = NT / 16;                // n8 tiles per warp (8, 4 or 2)
    constexpr int HSB  = 16384 + NT * 128;       // stage bytes per half
    constexpr int NSTG = (NT == 128) ? 3 : 4;    // ring depth per half
    constexpr uint32_t TXB = (uint32_t)HSB;

    __shared__ uint64_t mbF[2][4], mbE[2][4];

    const int tid   = threadIdx.x;
    const int warp  = tid >> 5;
    const int lane  = tid & 31;
    const int half  = warp >> 3;
    const int hwarp = warp & 7;
    const int lq    = lane >> 2;
    const int lr    = lane & 3;
    const int warpM = hwarp >> 1;                // 0..3 (32-row tiles)
    const int warpN = hwarp & 1;

    const uint32_t smH_b = s2u(dsm) + half * (NSTG * HSB);
    const uint32_t mbF_b = s2u(&mbF[half][0]);
    const uint32_t mbE_b = s2u(&mbE[half][0]);

    if (tid == 0) {
        #pragma unroll
        for (int h = 0; h < 2; h++)
            #pragma unroll
            for (int s = 0; s < NSTG; s++) {
                mbar_init(s2u(&mbF[h][s]), 1);   // tx-tracked fill
                mbar_init(s2u(&mbE[h][s]), 8);   // 8 consumer warps per half
            }
    }
    __syncthreads();

    const bool prod = (hwarp == 0 && lane == 0);

    auto issue = [&](int s, int t) {             // producer thread only
        const __half* A = (t < 64) ? A0 : A1;
        const __half* W = (t < 64) ? W0p : W1p;
        const int tt = t & 63;
        const uint32_t mb = mbF_b + 8 * s;
        const uint32_t dA = smH_b + s * HSB;
        mbar_expect(mb, TXB);
        bulkcp(dA, A + (size_t)(tt * 256 + half * 128) * 64, 16384, mb);
        bulkcp(dA + 16384, W + (size_t)tt * (NT * 64), NT * 128, mb);
    };

    if (prod) {
        #pragma unroll
        for (int s = 0; s < NSTG; s++) issue(s, s);
    }

    // fragment addressing (rows local to half; W region at +16384)
    const int msk = lane & 7;
    const int aKh = lane >> 4;
    const int bKh = (lane >> 3) & 1;
    int aByte[2];
    #pragma unroll
    for (int mi = 0; mi < 2; mi++) {
        int row = warpM * 32 + mi * 16 + (lane & 7) + 8 * ((lane >> 3) & 1);
        aByte[mi] = row * 128;
    }
    int bByte[NI / 2];
    #pragma unroll
    for (int j = 0; j < NI / 2; j++) {
        int row = 128 + warpN * (NI * 8) + j * 16 + (lane & 7) + 8 * (lane >> 4);
        bByte[j] = row * 128;
    }
    uint32_t aCh[4], bCh[4];                     // per-ks swizzled chunk offsets
    #pragma unroll
    for (int ks = 0; ks < 4; ks++) {
        aCh[ks] = (uint32_t)(((2 * ks + aKh) ^ msk) << 4);
        bCh[ks] = (uint32_t)(((2 * ks + bKh) ^ msk) << 4);
    }

    float acc[2][NI][4];
    #pragma unroll
    for (int mi = 0; mi < 2; mi++)
        #pragma unroll
        for (int ni = 0; ni < NI; ni++)
            #pragma unroll
            for (int f = 0; f < 4; f++) acc[mi][ni][f] = 0.0f;

    uint32_t afr[2][2][4];
    uint32_t bfr[2][NI / 2][4];
    auto load_frag = [&](uint32_t stB, int ks, int pb) {
        #pragma unroll
        for (int mi = 0; mi < 2; mi++)
            ldsm4(afr[pb][mi], stB + aByte[mi] + aCh[ks]);
        #pragma unroll
        for (int j = 0; j < NI / 2; j++)
            ldsm4(bfr[pb][j], stB + bByte[j] + bCh[ks]);
    };

    int st = 0;
    uint32_t ph = 0;
    for (int t = 0; t < nTiles; t++) {
        mbar_wait(mbF_b + 8 * st, ph);

        const uint32_t stB = smH_b + (uint32_t)(st * HSB);
        load_frag(stB, 0, 0);
        #pragma unroll
        for (int ks = 0; ks < 4; ks++) {
            const int pb = ks & 1;
            if (ks < 3) load_frag(stB, ks + 1, pb ^ 1);
            #pragma unroll
            for (int mi = 0; mi < 2; mi++)
                #pragma unroll
                for (int ni = 0; ni < NI; ni++)
                    mma16(acc[mi][ni], afr[pb][mi], &bfr[pb][ni >> 1][(ni & 1) * 2]);
        }

        if (lane == 0) mbar_arrive(mbE_b + 8 * st);
        if (prod && t + NSTG < nTiles) {
            mbar_wait(mbE_b + 8 * st, ph);       // all 8 warps done with stage st
            issue(st, t + NSTG);
        }
        if (++st == NSTG) { st = 0; ph ^= 1; }
    }

    // ---- fused epilogue (each output element owned by this block) ----
    #pragma unroll
    for (int mi = 0; mi < 2; mi++) {
        #pragma unroll
        for (int ni = 0; ni < NI; ni++) {
            int r = half * 128 + warpM * 32 + mi * 16 + lq;
            int c0 = nBase + warpN * (NI * 8) + ni * 8 + 2 * lr;
            #pragma unroll
            for (int h = 0; h < 2; h++) {
                int rr = r + 8 * h;
                float y0 = acc[mi][ni][2 * h + 0];
                float y1 = acc[mi][ni][2 * h + 1];
                if (RAW) {
                    size_t idx = (size_t)rr * DIM + c0;
                    *(float2*)(rawOut + idx) = make_float2(y0, y1);
                } else {
                    y0 += bias[c0];
                    y1 += bias[c0 + 1];
                    if (topP) {
                        size_t idx = (size_t)rr * DIM + c0;
                        y0 += topP[idx]; y1 += topP[idx + 1];
                    }
                    // packed-swizzled panel offset (same layout as init/bulk loads)
                    uint32_t off = (uint32_t)(((c0 >> 6) * 256 + rr) * 64
                                   + ((((c0 & 63) >> 3) ^ (rr & 7)) * 8) + (c0 & 7));
                    __half2 o2 = *(const __half2*)(oldPan + off);
                    float n0 = fminf(fmaxf(0.5f * __half2float(o2.x) + 0.5f * y0, 0.0f), 1.0f);
                    float n1 = fminf(fmaxf(0.5f * __half2float(o2.y) + 0.5f * y1, 0.0f), 1.0f);
                    *(__half2*)(newPan + off) = __floats2half2_rn(n0, n1);
                }
            }
        }
    }
}

// -------- one relaxation step: 128 equal-work blocks, one wave --------
__global__ void __launch_bounds__(512, 1) step_kernel(
    int p, const float* __restrict__ b0, const float* __restrict__ b2,
    const float* __restrict__ b4)
{
    extern __shared__ __align__(1024) char dsm[];
    const int bid = blockIdx.x;
    const int q = p ^ 1;
    if (bid < 32) {                 // s0' <- clip(.5 s0 + .5 (s1 @ W0^T + b0))
        const int nB = bid * 128;
        gemm_unit<128, false>(dsm, 64, g_sh[p][1], gW0 + (size_t)nB * DIM,
                              g_sh[p][1], gW0 + (size_t)nB * DIM, nB,
                              g_sh[p][0], g_sh[q][0], b0, nullptr, nullptr);
    } else if (bid < 96) {          // s1' <- clip(.5 s1 + .5 (s2 @ W2^T + s0 @ W1^T + b2))
        const int nB = (bid - 32) * 64;
        gemm_unit<64, false>(dsm, 128, g_sh[p][2], gW2 + (size_t)nB * DIM,
                             g_sh[p][0], gW1 + (size_t)nB * DIM, nB,
                             g_sh[p][1], g_sh[q][1], b2, nullptr, nullptr);
    } else {                        // s2' <- clip(.5 s2 + .5 (s1 @ W3^T + top + b4))
        const int nB = (bid - 96) * 128;
        gemm_unit<128, false>(dsm, 64, g_sh[p][1], gW3 + (size_t)nB * DIM,
                              g_sh[p][1], gW3 + (size_t)nB * DIM, nB,
                              g_sh[p][2], g_sh[q][2], b4, g_top, nullptr);
    }
}

// top = s3 @ W4^T over 128 blocks of N=32 (one wave)
__global__ void __launch_bounds__(512, 1) top_kernel()
{
    extern __shared__ __align__(1024) char dsm[];
    const int nB = blockIdx.x * 32;
    gemm_unit<32, true>(dsm, 64, g_s3h, gW4 + (size_t)nB * DIM,
                        g_s3h, gW4 + (size_t)nB * DIM, nB,
                        nullptr, nullptr, nullptr, nullptr, g_top);
}

// -------- setup: pack + swizzle weights and state --------
__global__ void wconv_kernel(const float* __restrict__ w0, const float* __restrict__ w1,
                             const float* __restrict__ w2, const float* __restrict__ w3,
                             const float* __restrict__ w4)
{
    const float* src;
    __half* dst;
    int ntShift;                       // log2(NTp)
    switch (blockIdx.y) {
        case 0: src = w0; dst = gW0; ntShift = 7; break;
        case 1: src = w1; dst = gW1; ntShift = 6; break;
        case 2: src = w2; dst = gW2; ntShift = 6; break;
        case 3: src = w3; dst = gW3; ntShift = 7; break;
        default: src = w4; dst = gW4; ntShift = 5; break;
    }
    const int id = blockIdx.x * blockDim.x + threadIdx.x;   // 0 .. 2M-1 (16B chunks)
    const int n  = id >> 9;
    const int kc = id & 511;
    float4 v0 = *(const float4*)(src + (size_t)n * DIM + kc * 8);
    float4 v1 = *(const float4*)(src + (size_t)n * DIM + kc * 8 + 4);
    __half2 h[4] = { __floats2half2_rn(v0.x, v0.y), __floats2half2_rn(v0.z, v0.w),
                     __floats2half2_rn(v1.x, v1.y), __floats2half2_rn(v1.z, v1.w) };
    const int NTp = 1 << ntShift;
    const int row = n & (NTp - 1);
    const int nT  = n >> ntShift;
    const int kT  = kc >> 3;
    const int ch  = kc & 7;
    size_t off = ((size_t)(nT * 64 + kT) * NTp + row) * 64 + (size_t)((ch ^ (row & 7)) * 8);
    *(uint4*)(dst + off) = *(uint4*)h;
}

__global__ void init_kernel(const float* __restrict__ s0, const float* __restrict__ s1,
                            const float* __restrict__ s2, const float* __restrict__ s3)
{
    const int layer = blockIdx.y;      // 0..3 (3 = s3)
    const float* src = (layer == 0) ? s0 : (layer == 1) ? s1 : (layer == 2) ? s2 : s3;
    __half* pan = (layer == 3) ? g_s3h : g_sh[0][layer];
    const int id = blockIdx.x * blockDim.x + threadIdx.x;   // 0 .. BD/8-1
    const int row = id >> 9;
    const int kc  = id & 511;
    float4 v0 = *(const float4*)(src + (size_t)row * DIM + kc * 8);
    float4 v1 = *(const float4*)(src + (size_t)row * DIM + kc * 8 + 4);
    __half2 h[4] = { __floats2half2_rn(v0.x, v0.y), __floats2half2_rn(v0.z, v0.w),
                     __floats2half2_rn(v1.x, v1.y), __floats2half2_rn(v1.z, v1.w) };
    size_t off = ((size_t)(kc >> 3) * 256 + row) * 64 + (size_t)(((kc & 7) ^ (row & 7)) * 8);
    *(uint4*)(pan + off) = *(uint4*)h;
}

// unpack fp16 panels (final state in buffer 0) -> fp32 row-major output
__global__ void out_kernel(float* __restrict__ out)
{
    const int layer = blockIdx.y;      // 0..2
    const __half* pan = g_sh[0][layer];
    const int id = blockIdx.x * blockDim.x + threadIdx.x;   // 0 .. BD/8-1
    const int row = id >> 9;
    const int kc  = id & 511;
    size_t off = ((size_t)(kc >> 3) * 256 + row) * 64 + (size_t)(((kc & 7) ^ (row & 7)) * 8);
    uint4 u = *(const uint4*)(pan + off);
    const __half2* h = (const __half2*)&u;
    float* dst = out + (size_t)layer * BD + (size_t)row * DIM + kc * 8;
    float2 f0 = __half22float2(h[0]);
    float2 f1 = __half22float2(h[1]);
    float2 f2 = __half22float2(h[2]);
    float2 f3 = __half22float2(h[3]);
    *(float4*)(dst)     = make_float4(f0.x, f0.y, f1.x, f1.y);
    *(float4*)(dst + 4) = make_float4(f2.x, f2.y, f3.x, f3.y);
}

extern "C" void kernel_launch(void* const* d_in, const int* in_sizes, int n_in,
                              void* d_out, int out_size)
{
    const float* s0 = (const float*)d_in[0];
    const float* s1 = (const float*)d_in[1];
    const float* s2 = (const float*)d_in[2];
    const float* s3 = (const float*)d_in[3];
    const float* W0 = (const float*)d_in[4];
    const float* b0 = (const float*)d_in[5];
    const float* W1 = (const float*)d_in[6];
    const float* W2 = (const float*)d_in[7];
    const float* b2 = (const float*)d_in[8];
    const float* W3 = (const float*)d_in[9];
    const float* W4 = (const float*)d_in[10];
    const float* b4 = (const float*)d_in[11];

    static_assert(SMEM_BYTES <= 227 * 1024, "smem budget");
    cudaFuncSetAttribute(step_kernel, cudaFuncAttributeMaxDynamicSharedMemorySize, SMEM_BYTES);
    cudaFuncSetAttribute(top_kernel,  cudaFuncAttributeMaxDynamicSharedMemorySize, SMEM_BYTES);

    wconv_kernel<<<dim3(DIM * DIM / 8 / 256, 5), 256>>>(W0, W1, W2, W3, W4);
    init_kernel<<<dim3(BD / 8 / 256, 4), 256>>>(s0, s1, s2, s3);

    top_kernel<<<128, 512, SMEM_BYTES>>>();

    for (int t = 0; t < NSTEPS; t++)
        step_kernel<<<128, 512, SMEM_BYTES>>>(t & 1, b0, b2, b4);

    out_kernel<<<dim3(BD / 8 / 256, 3), 256>>>((float*)d_out);
}